// round 9
// baseline (speedup 1.0000x reference)
#include <cuda_runtime.h>
#include <cuda_fp16.h>
#include <cstdint>

#define NN 40000
#define NE 640000
#define DD 128
#define LL 3
#define GRID 148
#define NTILES (NN / 64)          // 625 exact

// ---------------- scratch (static __device__, no allocation) ----------------
__device__ __align__(256) float  g_A[NN * DD];    // x @ psi_top + psi_b (by dst)
__device__ __align__(256) __half g_Bh[NN * DD];   // x @ psi_bot, fp16   (by src)
__device__ __align__(256) float  g_agg[NN * DD];  // scatter-mean result
__device__ __align__(256) float  g_xa[NN * DD];   // x double buffer 0
__device__ __align__(256) float  g_xb[NN * DD];   // x double buffer 1
__device__ float g_invdeg[NN];
__device__ int   g_deg[NN];
__device__ int   g_rowptr[NN + 1];
__device__ int   g_cursor[NN];
__device__ int   g_esrc[NE];

__device__ __forceinline__ float* resolve_buf(int id) {
    switch (id) {
        case 0: return g_A;
        case 2: return g_agg;
        case 3: return g_xa;
        case 4: return g_xb;
        default: return nullptr;
    }
}

__device__ __forceinline__ uint32_t f2tf32(float f) {
    uint32_t u;
    asm("cvt.rna.tf32.f32 %0, %1;" : "=r"(u) : "f"(f));
    return u;
}

#define CP16(dst_u32, src_ptr) \
    asm volatile("cp.async.cg.shared.global [%0], [%1], 16;\n" \
                 :: "r"(dst_u32), "l"(src_ptr))

// ---------------- CSR build ----------------
__global__ void zero_deg_kernel() {
    int i = blockIdx.x * blockDim.x + threadIdx.x;
    if (i < NN) g_deg[i] = 0;
}

__global__ void hist_kernel(const int* __restrict__ ei) {
    int e = blockIdx.x * blockDim.x + threadIdx.x;
    if (e < NE) {
        unsigned d = (unsigned)ei[NE + e];
        if (d < NN) atomicAdd(&g_deg[d], 1);
    }
}

__global__ void scan_kernel() {
    const int PER = 40;
    int tid = threadIdx.x;
    int lane = tid & 31, w = tid >> 5;
    int base = tid * PER;

    int total = 0;
    for (int j = 0; j < PER; j++) {
        int i = base + j;
        if (i < NN) total += g_deg[i];
    }
    int incl = total;
    #pragma unroll
    for (int off = 1; off < 32; off <<= 1) {
        int t = __shfl_up_sync(0xFFFFFFFFu, incl, off);
        if (lane >= off) incl += t;
    }
    __shared__ int wsum[32];
    if (lane == 31) wsum[w] = incl;
    __syncthreads();
    if (w == 0) {
        int v = wsum[lane];
        #pragma unroll
        for (int off = 1; off < 32; off <<= 1) {
            int t = __shfl_up_sync(0xFFFFFFFFu, v, off);
            if (lane >= off) v += t;
        }
        wsum[lane] = v;
    }
    __syncthreads();
    int run = incl - total + (w > 0 ? wsum[w - 1] : 0);
    for (int j = 0; j < PER; j++) {
        int i = base + j;
        if (i < NN) {
            int v = g_deg[i];
            g_rowptr[i] = run;
            g_cursor[i] = run;
            g_invdeg[i] = 1.0f / (float)(v > 1 ? v : 1);
            run += v;
        }
    }
    if (tid == 1023) g_rowptr[NN] = run;
}

__global__ void fill_kernel(const int* __restrict__ ei) {
    int e = blockIdx.x * blockDim.x + threadIdx.x;
    if (e < NE) {
        unsigned dst = (unsigned)ei[NE + e];
        unsigned src = (unsigned)ei[e];
        if (dst < NN && src < NN) {
            int pos = atomicAdd(&g_cursor[dst], 1);
            g_esrc[pos] = (int)src;
        }
    }
}

// ---------------- edge aggregation v2: warp/node, shfl-broadcast indices ----
// agg[i] = inv_deg[i] * sum_{e} relu(A[i] + B[src_e]);  B stored fp16
__global__ void agg_kernel() {
    int gt = blockIdx.x * blockDim.x + threadIdx.x;
    int node = gt >> 5;
    int lane = threadIdx.x & 31;
    if (node >= NN) return;
    int c = lane << 2;
    const float4 a = *(const float4*)&g_A[node * DD + c];
    float4 acc = make_float4(0.f, 0.f, 0.f, 0.f);
    int e0 = g_rowptr[node];
    int e1 = g_rowptr[node + 1];
    for (int base = e0; base < e1; base += 32) {
        int myidx = (base + lane < e1) ? g_esrc[base + lane] : 0;
        int cnt = e1 - base; if (cnt > 32) cnt = 32;
        for (int j = 0; j < cnt; ++j) {
            int s = __shfl_sync(0xFFFFFFFFu, myidx, j);
            uint2 hb = *(const uint2*)&g_Bh[s * DD + c];   // 4 halves
            float2 b01 = __half22float2(*(__half2*)&hb.x);
            float2 b23 = __half22float2(*(__half2*)&hb.y);
            acc.x += fmaxf(a.x + b01.x, 0.f);
            acc.y += fmaxf(a.y + b01.y, 0.f);
            acc.z += fmaxf(a.z + b23.x, 0.f);
            acc.w += fmaxf(a.w + b23.y, 0.f);
        }
    }
    float id = g_invdeg[node];
    float4 o = make_float4(acc.x * id, acc.y * id, acc.z * id, acc.w * id);
    *(float4*)&g_agg[node * DD + c] = o;
}

// ---------------- persistent W-resident pipelined tf32 GEMM -----------------
// PSI:  out cols [0..127] -> g_A fp32 (+biasA), [128..255] -> g_Bh fp16
// else: out = f(sum_s X_s @ W_s + bias) (+res), BN=128
template <int NSRC, bool RELU, bool RES, bool HASBIAS, bool PSI>
__global__ void __launch_bounds__(512) gemm_persist(
    const float* __restrict__ Xext, const float* __restrict__ W1,
    const float* __restrict__ W2, const float* __restrict__ bias,
    float* __restrict__ OutExt,
    int x1_id, int x2_id, int res_id, int out_id)
{
    constexpr int BN = PSI ? 256 : 128;
    constexpr int WROWS = PSI ? 128 : NSRC * 128;
    constexpr int WS = BN + 8;
    constexpr int NF = BN / 64;
    constexpr int NCHUNK = NSRC * 4;
    constexpr int LOG2NC = (NCHUNK == 8) ? 3 : 2;
    constexpr int XST = 64 * 36;

    extern __shared__ __align__(16) unsigned char sh_raw[];
    float*    Xsm = (float*)sh_raw;                       // [4][64][36]
    uint32_t* Wsm = (uint32_t*)(sh_raw + 4 * XST * 4);    // [WROWS][WS] tf32

    const float* X1 = (x1_id < 0) ? Xext : resolve_buf(x1_id);
    const float* X2 = (NSRC == 2) ? resolve_buf(x2_id) : nullptr;
    const float* res = RES ? ((res_id < 0) ? Xext : resolve_buf(res_id)) : nullptr;
    float* out = (out_id < 0) ? OutExt : resolve_buf(out_id);

    int tid = threadIdx.x;
    int lane = tid & 31;
    int wid = tid >> 5;
    int warp_m = wid >> 3;           // 0..1
    int warp_n = wid & 7;            // 0..7
    int g = lane >> 2;               // 0..7
    int tg = lane & 3;               // 0..3
    int b = blockIdx.x;

    uint32_t xbase;
    { uint64_t tmp = __cvta_generic_to_shared(Xsm); xbase = (uint32_t)tmp; }

    // ---- load W into smem, pre-converted to tf32 ----
    {
        constexpr int NV4 = WROWS * BN / 4 / 512;
        #pragma unroll
        for (int i = 0; i < NV4; i++) {
            int f = tid + i * 512;
            int r, c;
            const float* src;
            if (PSI) {
                r = f >> 6; c = (f & 63) << 2;
                src = (c < 128) ? (W1 + r * 128 + c) : (W2 + r * 128 + (c - 128));
            } else if (NSRC == 2) {
                r = f >> 5; c = (f & 31) << 2;
                src = (r < 128) ? (W1 + r * 128 + c) : (W2 + (r - 128) * 128 + c);
            } else {
                r = f >> 5; c = (f & 31) << 2;
                src = W1 + r * 128 + c;
            }
            float4 v = *(const float4*)src;
            uint4 u = make_uint4(f2tf32(v.x), f2tf32(v.y), f2tf32(v.z), f2tf32(v.w));
            *(uint4*)&Wsm[r * WS + c] = u;
        }
    }

    float bv[NF][2];
    #pragma unroll
    for (int nf = 0; nf < NF; nf++) {
        int colg = warp_n * (NF * 8) + nf * 8 + tg * 2;
        bv[nf][0] = 0.f; bv[nf][1] = 0.f;
        if (PSI) {
            if (colg < 128) { bv[nf][0] = bias[colg]; bv[nf][1] = bias[colg + 1]; }
        } else if (HASBIAS) {
            bv[nf][0] = bias[colg]; bv[nf][1] = bias[colg + 1];
        }
    }

    int nt = (NTILES - b + GRID - 1) / GRID;
    int TOTAL = nt * NCHUNK;

    int xrow = tid >> 3;
    int xkq = (tid & 7) << 2;

    auto issue = [&](int ci) {
        int t = b + (ci >> LOG2NC) * GRID;
        int k = ci & (NCHUNK - 1);
        const float* Xp = (NSRC == 2 && k >= 4) ? X2 : X1;
        int k0 = (k & 3) * 32;
        const float* src = Xp + (size_t)(t * 64 + xrow) * 128 + k0 + xkq;
        uint32_t dst = xbase + (((ci & 3) * XST + xrow * 36 + xkq) << 2);
        CP16(dst, src);
        asm volatile("cp.async.commit_group;\n" ::);
    };

    issue(0); issue(1); issue(2);

    float C[2][NF][4];
    #pragma unroll
    for (int i = 0; i < 2; i++)
        #pragma unroll
        for (int j = 0; j < NF; j++)
            #pragma unroll
            for (int q = 0; q < 4; q++) C[i][j][q] = 0.f;

    for (int ci = 0; ci < TOTAL; ci++) {
        int nxt = ci + 3; if (nxt > TOTAL - 1) nxt = TOTAL - 1;
        issue(nxt);
        asm volatile("cp.async.wait_group 3;\n" ::: "memory");
        __syncthreads();

        int k = ci & (NCHUNK - 1);
        int wbase = (PSI ? 0 : (k >> 2) * 128) + (k & 3) * 32;
        const float* Xst = Xsm + (ci & 3) * XST;

        #pragma unroll
        for (int kg = 0; kg < 4; kg++) {
            int kk = kg * 8;
            uint32_t a[2][4];
            #pragma unroll
            for (int mf = 0; mf < 2; mf++) {
                int r = warp_m * 32 + mf * 16 + g;
                a[mf][0] = f2tf32(Xst[r * 36 + kk + tg]);
                a[mf][1] = f2tf32(Xst[(r + 8) * 36 + kk + tg]);
                a[mf][2] = f2tf32(Xst[r * 36 + kk + tg + 4]);
                a[mf][3] = f2tf32(Xst[(r + 8) * 36 + kk + tg + 4]);
            }
            #pragma unroll
            for (int nf = 0; nf < NF; nf++) {
                int col = warp_n * (NF * 8) + nf * 8 + g;
                int wr = wbase + kk + tg;
                uint32_t b0 = Wsm[wr * WS + col];
                uint32_t b1 = Wsm[(wr + 4) * WS + col];
                #pragma unroll
                for (int mf = 0; mf < 2; mf++) {
                    asm volatile(
                        "mma.sync.aligned.m16n8k8.row.col.f32.tf32.tf32.f32 "
                        "{%0,%1,%2,%3}, {%4,%5,%6,%7}, {%8,%9}, {%0,%1,%2,%3};"
                        : "+f"(C[mf][nf][0]), "+f"(C[mf][nf][1]),
                          "+f"(C[mf][nf][2]), "+f"(C[mf][nf][3])
                        : "r"(a[mf][0]), "r"(a[mf][1]), "r"(a[mf][2]), "r"(a[mf][3]),
                          "r"(b0), "r"(b1));
                }
            }
        }

        if (k == NCHUNK - 1) {
            int t = b + (ci >> LOG2NC) * GRID;
            int m0 = t * 64;
            #pragma unroll
            for (int nf = 0; nf < NF; nf++) {
                int colg = warp_n * (NF * 8) + nf * 8 + tg * 2;
                #pragma unroll
                for (int mf = 0; mf < 2; mf++) {
                    #pragma unroll
                    for (int h = 0; h < 2; h++) {
                        int m = m0 + warp_m * 32 + mf * 16 + g + h * 8;
                        float v0 = C[mf][nf][h * 2 + 0] + bv[nf][0];
                        float v1 = C[mf][nf][h * 2 + 1] + bv[nf][1];
                        if (RELU) { v0 = fmaxf(v0, 0.f); v1 = fmaxf(v1, 0.f); }
                        if (RES) {
                            float2 r = *(const float2*)&res[(size_t)m * 128 + colg];
                            v0 += r.x; v1 += r.y;
                        }
                        if (PSI && colg >= 128) {
                            *(__half2*)&g_Bh[(size_t)m * 128 + (colg - 128)] =
                                __floats2half2_rn(v0, v1);
                        } else {
                            float* outp = PSI ? g_A : out;
                            *(float2*)&outp[(size_t)m * 128 + colg] = make_float2(v0, v1);
                        }
                        C[mf][nf][h * 2 + 0] = 0.f;
                        C[mf][nf][h * 2 + 1] = 0.f;
                    }
                }
            }
        }
        __syncthreads();
    }
}

// ---------------- launch ----------------
extern "C" void kernel_launch(void* const* d_in, const int* in_sizes, int n_in,
                              void* d_out, int out_size) {
    const float* x     = (const float*)d_in[0];
    const int*   ei    = (const int*)d_in[1];
    const float* psi_w = (const float*)d_in[2];
    const float* psi_b = (const float*)d_in[3];
    const float* phi_w = (const float*)d_in[4];
    const float* phi_b = (const float*)d_in[5];
    const float* dp_w  = (const float*)d_in[6];
    const float* dp_b  = (const float*)d_in[7];
    float* out = (float*)d_out;

    const int XBYTES   = 4 * 64 * 36 * 4;
    const int PSI_SM   = XBYTES + 128 * 264 * 4;
    const int PHI_SM   = XBYTES + 256 * 136 * 4;
    const int DP_SM    = XBYTES + 128 * 136 * 4;

    cudaFuncSetAttribute(gemm_persist<1, false, false, true, true>,
                         cudaFuncAttributeMaxDynamicSharedMemorySize, PSI_SM);
    cudaFuncSetAttribute(gemm_persist<2, true, true, true, false>,
                         cudaFuncAttributeMaxDynamicSharedMemorySize, PHI_SM);
    cudaFuncSetAttribute(gemm_persist<1, false, false, true, false>,
                         cudaFuncAttributeMaxDynamicSharedMemorySize, DP_SM);

    zero_deg_kernel<<<(NN + 255) / 256, 256>>>();
    hist_kernel<<<(NE + 255) / 256, 256>>>(ei);
    scan_kernel<<<1, 1024>>>();
    fill_kernel<<<(NE + 255) / 256, 256>>>(ei);

    const int AGG_BLOCKS = (NN * 32 + 255) / 256;

    // buffer ids: 0=g_A 2=g_agg 3=g_xa 4=g_xb, -1=external
    int xin_id = -1;
    for (int l = 0; l < LL; l++) {
        const float* psiT = psi_w + (size_t)l * 256 * 128;
        const float* psiB = psiT + 128 * 128;
        gemm_persist<1, false, false, true, true><<<GRID, 512, PSI_SM>>>(
            x, psiT, psiB, psi_b + (size_t)l * 128, nullptr,
            xin_id, -1, -1, 0);
        agg_kernel<<<AGG_BLOCKS, 256>>>();
        const float* phiT = phi_w + (size_t)l * 256 * 128;
        const float* phiB = phiT + 128 * 128;
        int xout_id = 3 + (l & 1);
        gemm_persist<2, true, true, true, false><<<GRID, 512, PHI_SM>>>(
            x, phiT, phiB, phi_b + (size_t)l * 128, nullptr,
            xin_id, 2, xin_id, xout_id);
        xin_id = xout_id;
    }
    gemm_persist<1, false, false, true, false><<<GRID, 512, DP_SM>>>(
        x, dp_w, nullptr, dp_b, out,
        xin_id, -1, -1, -1);
}

// round 12
// speedup vs baseline: 1.1939x; 1.1939x over previous
#include <cuda_runtime.h>
#include <cuda_fp16.h>
#include <cstdint>
#include <cstring>

#define NN 40000
#define NE 640000
#define DD 128
#define LL 3
#define GRID 148
#define NTILES (NN / 64)          // 625 exact
#define XSTRIDE 40                // floats; conflict-free LDS.64 A-frags
#define XST (64 * XSTRIDE)        // floats per X stage

// ---------------- scratch (static __device__, no allocation) ----------------
__device__ __align__(256) float  g_A[NN * DD];    // psi-top out, fp32 (by dst)
__device__ __align__(256) __half g_Bh[NN * DD];   // psi-bot out, fp16 (by src)
__device__ __align__(256) float  g_agg[NN * DD];  // scatter-mean result
__device__ __align__(256) float  g_xa[NN * DD];
__device__ __align__(256) float  g_xb[NN * DD];
__device__ float g_invdeg[NN];
__device__ int   g_deg[NN];
__device__ int   g_rowptr[NN + 1];
__device__ int   g_cursor[NN];
__device__ int   g_esrc[NE];

__device__ __forceinline__ float* resolve_buf(int id) {
    switch (id) {
        case 0: return g_A;
        case 2: return g_agg;
        case 3: return g_xa;
        case 4: return g_xb;
        default: return nullptr;
    }
}

__device__ __forceinline__ uint32_t h2u(__half2 h) {
    uint32_t u;
    memcpy(&u, &h, 4);
    return u;
}

#define CP16(dst_u32, src_ptr) \
    asm volatile("cp.async.cg.shared.global [%0], [%1], 16;\n" \
                 :: "r"(dst_u32), "l"(src_ptr))

// ---------------- CSR build ----------------
__global__ void zero_deg_kernel() {
    int i = blockIdx.x * blockDim.x + threadIdx.x;
    if (i < NN) g_deg[i] = 0;
}

__global__ void hist_kernel(const int* __restrict__ ei) {
    int e = blockIdx.x * blockDim.x + threadIdx.x;
    if (e < NE) {
        unsigned d = (unsigned)ei[NE + e];
        if (d < NN) atomicAdd(&g_deg[d], 1);
    }
}

__global__ void scan_kernel() {
    const int PER = 40;
    int tid = threadIdx.x;
    int lane = tid & 31, w = tid >> 5;
    int base = tid * PER;

    int total = 0;
    for (int j = 0; j < PER; j++) {
        int i = base + j;
        if (i < NN) total += g_deg[i];
    }
    int incl = total;
    #pragma unroll
    for (int off = 1; off < 32; off <<= 1) {
        int t = __shfl_up_sync(0xFFFFFFFFu, incl, off);
        if (lane >= off) incl += t;
    }
    __shared__ int wsum[32];
    if (lane == 31) wsum[w] = incl;
    __syncthreads();
    if (w == 0) {
        int v = wsum[lane];
        #pragma unroll
        for (int off = 1; off < 32; off <<= 1) {
            int t = __shfl_up_sync(0xFFFFFFFFu, v, off);
            if (lane >= off) v += t;
        }
        wsum[lane] = v;
    }
    __syncthreads();
    int run = incl - total + (w > 0 ? wsum[w - 1] : 0);
    for (int j = 0; j < PER; j++) {
        int i = base + j;
        if (i < NN) {
            int v = g_deg[i];
            g_rowptr[i] = run;
            g_cursor[i] = run;
            g_invdeg[i] = 1.0f / (float)(v > 1 ? v : 1);
            run += v;
        }
    }
    if (tid == 1023) g_rowptr[NN] = run;
}

__global__ void fill_kernel(const int* __restrict__ ei) {
    int e = blockIdx.x * blockDim.x + threadIdx.x;
    if (e < NE) {
        unsigned dst = (unsigned)ei[NE + e];
        unsigned src = (unsigned)ei[e];
        if (dst < NN && src < NN) {
            int pos = atomicAdd(&g_cursor[dst], 1);
            g_esrc[pos] = (int)src;
        }
    }
}

// ---------------- edge aggregation: warp/node, simple loop, fp16 B ----------
__global__ void agg_kernel() {
    int gt = blockIdx.x * blockDim.x + threadIdx.x;
    int node = gt >> 5;
    int lane = threadIdx.x & 31;
    if (node >= NN) return;
    int c = lane << 2;
    const float4 a = *(const float4*)&g_A[node * DD + c];
    float4 acc = make_float4(0.f, 0.f, 0.f, 0.f);
    int e0 = g_rowptr[node];
    int e1 = g_rowptr[node + 1];
    #pragma unroll 4
    for (int e = e0; e < e1; ++e) {
        int s = g_esrc[e];
        uint2 hb = *(const uint2*)&g_Bh[s * DD + c];
        float2 b01 = __half22float2(*(__half2*)&hb.x);
        float2 b23 = __half22float2(*(__half2*)&hb.y);
        acc.x += fmaxf(a.x + b01.x, 0.f);
        acc.y += fmaxf(a.y + b01.y, 0.f);
        acc.z += fmaxf(a.z + b23.x, 0.f);
        acc.w += fmaxf(a.w + b23.y, 0.f);
    }
    float id = g_invdeg[node];
    float4 o = make_float4(acc.x * id, acc.y * id, acc.z * id, acc.w * id);
    *(float4*)&g_agg[node * DD + c] = o;
}

// ---------------- persistent W-resident pipelined fp16 GEMM -----------------
// mma.sync.m16n8k16.f32.f16.f16.f32; W pre-packed as half2 k-pairs in smem.
// PSI: out cols [0..127] -> g_A fp32 (+biasA), [128..255] -> g_Bh fp16
// else: out = f(sum_s X_s @ W_s + bias) (+res), BN=128
template <int NSRC, bool RELU, bool RES, bool HASBIAS, bool PSI>
__global__ void __launch_bounds__(512) gemm_persist(
    const float* __restrict__ Xext, const float* __restrict__ W1,
    const float* __restrict__ W2, const float* __restrict__ bias,
    float* __restrict__ OutExt,
    int x1_id, int x2_id, int res_id, int out_id)
{
    constexpr int BN = PSI ? 256 : 128;
    constexpr int KHROWS = (PSI ? 128 : NSRC * 128) / 2;   // half2 k-pair rows
    constexpr int WSH = BN + 8;                // half2 stride; ≡8 mod 32
    constexpr int NF = BN / 64;                // 4 (psi) or 2
    constexpr int NCHUNK = NSRC * 4;
    constexpr int LOG2NC = (NCHUNK == 8) ? 3 : 2;

    extern __shared__ __align__(16) unsigned char sh_raw[];
    float*    Xsm  = (float*)sh_raw;                        // [4][64][XSTRIDE]
    uint32_t* Whsm = (uint32_t*)(sh_raw + 4 * XST * 4);     // [KHROWS][WSH] half2

    const float* X1 = (x1_id < 0) ? Xext : resolve_buf(x1_id);
    const float* X2 = (NSRC == 2) ? resolve_buf(x2_id) : nullptr;
    const float* res = RES ? ((res_id < 0) ? Xext : resolve_buf(res_id)) : nullptr;
    float* out = (out_id < 0) ? OutExt : resolve_buf(out_id);

    int tid = threadIdx.x;
    int lane = tid & 31;
    int wid = tid >> 5;
    int warp_m = wid >> 3;           // 0..1
    int warp_n = wid & 7;            // 0..7
    int g = lane >> 2;               // 0..7
    int tg = lane & 3;               // 0..3
    int b = blockIdx.x;

    uint32_t xbase;
    { uint64_t tmp = __cvta_generic_to_shared(Xsm); xbase = (uint32_t)tmp; }

    // ---- pack W into smem as half2 k-pairs: Wh[kh][n] = (W[2kh][n], W[2kh+1][n])
    {
        constexpr int NQ = KHROWS * BN / 4 / 512;   // quads per thread
        #pragma unroll
        for (int i = 0; i < NQ; i++) {
            int f = tid + i * 512;
            int kh = f / (BN / 4);
            int c4 = (f % (BN / 4)) << 2;
            const float *r0p, *r1p;
            if (PSI) {
                const float* Wm = (c4 < 128) ? W1 : W2;
                int cc = (c4 < 128) ? c4 : c4 - 128;
                r0p = Wm + (2 * kh) * 128 + cc;
                r1p = Wm + (2 * kh + 1) * 128 + cc;
            } else if (NSRC == 2) {
                const float* Wm = (kh < 64) ? W1 : W2;
                int kk = (kh < 64) ? kh : kh - 64;
                r0p = Wm + (2 * kk) * 128 + c4;
                r1p = Wm + (2 * kk + 1) * 128 + c4;
            } else {
                r0p = W1 + (2 * kh) * 128 + c4;
                r1p = W1 + (2 * kh + 1) * 128 + c4;
            }
            float4 v0 = *(const float4*)r0p;
            float4 v1 = *(const float4*)r1p;
            uint4 u;
            u.x = h2u(__floats2half2_rn(v0.x, v1.x));
            u.y = h2u(__floats2half2_rn(v0.y, v1.y));
            u.z = h2u(__floats2half2_rn(v0.z, v1.z));
            u.w = h2u(__floats2half2_rn(v0.w, v1.w));
            *(uint4*)&Whsm[kh * WSH + c4] = u;
        }
    }

    float bv[NF][2];
    #pragma unroll
    for (int nf = 0; nf < NF; nf++) {
        int colg = warp_n * (NF * 8) + nf * 8 + tg * 2;
        bv[nf][0] = 0.f; bv[nf][1] = 0.f;
        if (PSI) {
            if (colg < 128) { bv[nf][0] = bias[colg]; bv[nf][1] = bias[colg + 1]; }
        } else if (HASBIAS) {
            bv[nf][0] = bias[colg]; bv[nf][1] = bias[colg + 1];
        }
    }

    int nt = (NTILES - b + GRID - 1) / GRID;
    int TOTAL = nt * NCHUNK;

    int xrow = tid >> 3;
    int xkq = (tid & 7) << 2;

    auto issue = [&](int ci) {
        int t = b + (ci >> LOG2NC) * GRID;
        int k = ci & (NCHUNK - 1);
        const float* Xp = (NSRC == 2 && k >= 4) ? X2 : X1;
        int k0 = (k & 3) * 32;
        const float* src = Xp + (size_t)(t * 64 + xrow) * 128 + k0 + xkq;
        uint32_t dst = xbase + (((ci & 3) * XST + xrow * XSTRIDE + xkq) << 2);
        CP16(dst, src);
        asm volatile("cp.async.commit_group;\n" ::);
    };

    issue(0); issue(1); issue(2);

    float C[2][NF][4];
    #pragma unroll
    for (int i = 0; i < 2; i++)
        #pragma unroll
        for (int j = 0; j < NF; j++)
            #pragma unroll
            for (int q = 0; q < 4; q++) C[i][j][q] = 0.f;

    for (int ci = 0; ci < TOTAL; ci++) {
        int nxt = ci + 3; if (nxt > TOTAL - 1) nxt = TOTAL - 1;
        issue(nxt);
        asm volatile("cp.async.wait_group 3;\n" ::: "memory");
        __syncthreads();

        int k = ci & (NCHUNK - 1);
        // kh base for this chunk (half2 k-pair units)
        int khchunk = (PSI ? 0 : (k >> 2) * 64) + (k & 3) * 16;
        const float* Xst = Xsm + (ci & 3) * XST;

        #pragma unroll
        for (int kg = 0; kg < 2; kg++) {          // two k16 groups per chunk
            int kk = kg * 16;                     // float-k offset in stage
            uint32_t a[2][4];
            #pragma unroll
            for (int mf = 0; mf < 2; mf++) {
                int r = warp_m * 32 + mf * 16 + g;
                float2 f0 = *(const float2*)&Xst[r * XSTRIDE + kk + 2 * tg];
                float2 f1 = *(const float2*)&Xst[(r + 8) * XSTRIDE + kk + 2 * tg];
                float2 f2 = *(const float2*)&Xst[r * XSTRIDE + kk + 8 + 2 * tg];
                float2 f3 = *(const float2*)&Xst[(r + 8) * XSTRIDE + kk + 8 + 2 * tg];
                a[mf][0] = h2u(__floats2half2_rn(f0.x, f0.y));
                a[mf][1] = h2u(__floats2half2_rn(f1.x, f1.y));
                a[mf][2] = h2u(__floats2half2_rn(f2.x, f2.y));
                a[mf][3] = h2u(__floats2half2_rn(f3.x, f3.y));
            }
            int khb = khchunk + kg * 8;
            #pragma unroll
            for (int nf = 0; nf < NF; nf++) {
                int col = warp_n * (NF * 8) + nf * 8 + g;
                uint32_t b0 = Whsm[(khb + tg) * WSH + col];
                uint32_t b1 = Whsm[(khb + tg + 4) * WSH + col];
                #pragma unroll
                for (int mf = 0; mf < 2; mf++) {
                    asm volatile(
                        "mma.sync.aligned.m16n8k16.row.col.f32.f16.f16.f32 "
                        "{%0,%1,%2,%3}, {%4,%5,%6,%7}, {%8,%9}, {%0,%1,%2,%3};"
                        : "+f"(C[mf][nf][0]), "+f"(C[mf][nf][1]),
                          "+f"(C[mf][nf][2]), "+f"(C[mf][nf][3])
                        : "r"(a[mf][0]), "r"(a[mf][1]), "r"(a[mf][2]), "r"(a[mf][3]),
                          "r"(b0), "r"(b1));
                }
            }
        }

        if (k == NCHUNK - 1) {
            int t = b + (ci >> LOG2NC) * GRID;
            int m0 = t * 64;
            #pragma unroll
            for (int nf = 0; nf < NF; nf++) {
                int colg = warp_n * (NF * 8) + nf * 8 + tg * 2;
                #pragma unroll
                for (int mf = 0; mf < 2; mf++) {
                    #pragma unroll
                    for (int h = 0; h < 2; h++) {
                        int m = m0 + warp_m * 32 + mf * 16 + g + h * 8;
                        float v0 = C[mf][nf][h * 2 + 0] + bv[nf][0];
                        float v1 = C[mf][nf][h * 2 + 1] + bv[nf][1];
                        if (RELU) { v0 = fmaxf(v0, 0.f); v1 = fmaxf(v1, 0.f); }
                        if (RES) {
                            float2 r = *(const float2*)&res[(size_t)m * 128 + colg];
                            v0 += r.x; v1 += r.y;
                        }
                        if (PSI && colg >= 128) {
                            *(__half2*)&g_Bh[(size_t)m * 128 + (colg - 128)] =
                                __floats2half2_rn(v0, v1);
                        } else {
                            float* outp = PSI ? g_A : out;
                            *(float2*)&outp[(size_t)m * 128 + colg] = make_float2(v0, v1);
                        }
                        C[mf][nf][h * 2 + 0] = 0.f;
                        C[mf][nf][h * 2 + 1] = 0.f;
                    }
                }
            }
        }
        __syncthreads();
    }
}

// ---------------- launch ----------------
extern "C" void kernel_launch(void* const* d_in, const int* in_sizes, int n_in,
                              void* d_out, int out_size) {
    const float* x     = (const float*)d_in[0];
    const int*   ei    = (const int*)d_in[1];
    const float* psi_w = (const float*)d_in[2];
    const float* psi_b = (const float*)d_in[3];
    const float* phi_w = (const float*)d_in[4];
    const float* phi_b = (const float*)d_in[5];
    const float* dp_w  = (const float*)d_in[6];
    const float* dp_b  = (const float*)d_in[7];
    float* out = (float*)d_out;

    const int XBYTES = 4 * XST * 4;                    // 40960
    const int PSI_SM = XBYTES + 64 * 264 * 4;          // 108544
    const int PHI_SM = XBYTES + 128 * 136 * 4;         // 110592
    const int DP_SM  = XBYTES + 64 * 136 * 4;          // 75776

    cudaFuncSetAttribute(gemm_persist<1, false, false, true, true>,
                         cudaFuncAttributeMaxDynamicSharedMemorySize, PSI_SM);
    cudaFuncSetAttribute(gemm_persist<2, true, true, true, false>,
                         cudaFuncAttributeMaxDynamicSharedMemorySize, PHI_SM);
    cudaFuncSetAttribute(gemm_persist<1, false, false, true, false>,
                         cudaFuncAttributeMaxDynamicSharedMemorySize, DP_SM);

    zero_deg_kernel<<<(NN + 255) / 256, 256>>>();
    hist_kernel<<<(NE + 255) / 256, 256>>>(ei);
    scan_kernel<<<1, 1024>>>();
    fill_kernel<<<(NE + 255) / 256, 256>>>(ei);

    const int AGG_BLOCKS = (NN * 32 + 255) / 256;

    int xin_id = -1;
    for (int l = 0; l < LL; l++) {
        const float* psiT = psi_w + (size_t)l * 256 * 128;
        const float* psiB = psiT + 128 * 128;
        gemm_persist<1, false, false, true, true><<<GRID, 512, PSI_SM>>>(
            x, psiT, psiB, psi_b + (size_t)l * 128, nullptr,
            xin_id, -1, -1, 0);
        agg_kernel<<<AGG_BLOCKS, 256>>>();
        const float* phiT = phi_w + (size_t)l * 256 * 128;
        const float* phiB = phiT + 128 * 128;
        int xout_id = 3 + (l & 1);
        gemm_persist<2, true, true, true, false><<<GRID, 512, PHI_SM>>>(
            x, phiT, phiB, phi_b + (size_t)l * 128, nullptr,
            xin_id, 2, xin_id, xout_id);
        xin_id = xout_id;
    }
    gemm_persist<1, false, false, true, false><<<GRID, 512, DP_SM>>>(
        x, dp_w, nullptr, dp_b, out,
        xin_id, -1, -1, -1);
}

// round 14
// speedup vs baseline: 1.2733x; 1.0665x over previous
#include <cuda_runtime.h>
#include <cuda_fp16.h>
#include <cstdint>
#include <cstring>

#define NN 40000
#define NE 640000
#define DD 128
#define LL 3
#define GRID 148
#define NTILES (NN / 64)          // 625 exact
#define XSTH (64 * 72)            // halves per X stage (row stride 72 halves)

// ---------------- scratch (static __device__, no allocation) ----------------
__device__ __align__(256) float  g_A[NN * DD];     // psi-top out, fp32 (by dst)
__device__ __align__(256) __half g_Bh[NN * DD];    // psi-bot out, fp16 (by src)
__device__ __align__(256) __half g_aggh[NN * DD];  // scatter-mean, fp16
__device__ __align__(256) float  g_xa[NN * DD];    // x fp32 (residual path)
__device__ __align__(256) float  g_xb[NN * DD];
__device__ __align__(256) __half g_xh0[NN * DD];   // fp16(x input)
__device__ __align__(256) __half g_xha[NN * DD];   // fp16 x double buffers
__device__ __align__(256) __half g_xhb[NN * DD];
__device__ float g_invdeg[NN];
__device__ int   g_deg[NN];
__device__ int   g_rowptr[NN + 1];
__device__ int   g_cursor[NN];
__device__ int   g_esrc[NE];

__device__ __forceinline__ float* resolve_buf(int id) {   // fp32
    switch (id) {
        case 0: return g_A;
        case 3: return g_xa;
        case 4: return g_xb;
        default: return nullptr;
    }
}
__device__ __forceinline__ __half* resolve_hbuf(int id) { // fp16
    switch (id) {
        case 0: return g_xh0;
        case 1: return g_xha;
        case 2: return g_xhb;
        case 3: return g_aggh;
        default: return nullptr;
    }
}

__device__ __forceinline__ uint32_t h2u(__half2 h) {
    uint32_t u;
    memcpy(&u, &h, 4);
    return u;
}

#define CP16(dst_u32, src_ptr) \
    asm volatile("cp.async.cg.shared.global [%0], [%1], 16;\n" \
                 :: "r"(dst_u32), "l"(src_ptr))

// ---------------- CSR build ----------------
__global__ void zero_deg_kernel() {
    int i = blockIdx.x * blockDim.x + threadIdx.x;
    if (i < NN) g_deg[i] = 0;
}

__global__ void hist_kernel(const int* __restrict__ ei) {
    int e = blockIdx.x * blockDim.x + threadIdx.x;
    if (e < NE) {
        unsigned d = (unsigned)ei[NE + e];
        if (d < NN) atomicAdd(&g_deg[d], 1);
    }
}

__global__ void scan_kernel() {
    const int PER = 40;
    int tid = threadIdx.x;
    int lane = tid & 31, w = tid >> 5;
    int base = tid * PER;

    int total = 0;
    for (int j = 0; j < PER; j++) {
        int i = base + j;
        if (i < NN) total += g_deg[i];
    }
    int incl = total;
    #pragma unroll
    for (int off = 1; off < 32; off <<= 1) {
        int t = __shfl_up_sync(0xFFFFFFFFu, incl, off);
        if (lane >= off) incl += t;
    }
    __shared__ int wsum[32];
    if (lane == 31) wsum[w] = incl;
    __syncthreads();
    if (w == 0) {
        int v = wsum[lane];
        #pragma unroll
        for (int off = 1; off < 32; off <<= 1) {
            int t = __shfl_up_sync(0xFFFFFFFFu, v, off);
            if (lane >= off) v += t;
        }
        wsum[lane] = v;
    }
    __syncthreads();
    int run = incl - total + (w > 0 ? wsum[w - 1] : 0);
    for (int j = 0; j < PER; j++) {
        int i = base + j;
        if (i < NN) {
            int v = g_deg[i];
            g_rowptr[i] = run;
            g_cursor[i] = run;
            g_invdeg[i] = 1.0f / (float)(v > 1 ? v : 1);
            run += v;
        }
    }
    if (tid == 1023) g_rowptr[NN] = run;
}

__global__ void fill_kernel(const int* __restrict__ ei) {
    int e = blockIdx.x * blockDim.x + threadIdx.x;
    if (e < NE) {
        unsigned dst = (unsigned)ei[NE + e];
        unsigned src = (unsigned)ei[e];
        if (dst < NN && src < NN) {
            int pos = atomicAdd(&g_cursor[dst], 1);
            g_esrc[pos] = (int)src;
        }
    }
}

// ---------------- x -> fp16 convert ----------------
__global__ void x2h_kernel(const float* __restrict__ x) {
    int i = (blockIdx.x * blockDim.x + threadIdx.x) * 8;
    if (i < NN * DD) {
        float4 v0 = *(const float4*)&x[i];
        float4 v1 = *(const float4*)&x[i + 4];
        uint4 u;
        u.x = h2u(__floats2half2_rn(v0.x, v0.y));
        u.y = h2u(__floats2half2_rn(v0.z, v0.w));
        u.z = h2u(__floats2half2_rn(v1.x, v1.y));
        u.w = h2u(__floats2half2_rn(v1.z, v1.w));
        *(uint4*)&g_xh0[i] = u;
    }
}

// ---------------- edge aggregation: warp/node, fp16 B, fp16 out ------------
__global__ void agg_kernel() {
    int gt = blockIdx.x * blockDim.x + threadIdx.x;
    int node = gt >> 5;
    int lane = threadIdx.x & 31;
    if (node >= NN) return;
    int c = lane << 2;
    const float4 a = *(const float4*)&g_A[node * DD + c];
    float4 acc = make_float4(0.f, 0.f, 0.f, 0.f);
    int e0 = g_rowptr[node];
    int e1 = g_rowptr[node + 1];
    #pragma unroll 4
    for (int e = e0; e < e1; ++e) {
        int s = g_esrc[e];
        uint2 hb = *(const uint2*)&g_Bh[s * DD + c];
        float2 b01 = __half22float2(*(__half2*)&hb.x);
        float2 b23 = __half22float2(*(__half2*)&hb.y);
        acc.x += fmaxf(a.x + b01.x, 0.f);
        acc.y += fmaxf(a.y + b01.y, 0.f);
        acc.z += fmaxf(a.z + b23.x, 0.f);
        acc.w += fmaxf(a.w + b23.y, 0.f);
    }
    float id = g_invdeg[node];
    uint2 o;
    o.x = h2u(__floats2half2_rn(acc.x * id, acc.y * id));
    o.y = h2u(__floats2half2_rn(acc.z * id, acc.w * id));
    *(uint2*)&g_aggh[node * DD + c] = o;
}

// ---------------- persistent W-resident pipelined fp16 GEMM -----------------
// Inputs fp16 (ldmatrix A-frags); W pre-packed half2 k-pairs in smem.
// PSI: out cols [0..127] -> g_A fp32 (+biasA), [128..255] -> g_Bh fp16
// else: out = f(sum_s X_s @ W_s + bias) (+res fp32); writes fp32 out and
//       optionally fp16 outh (dual write for next-layer GEMM operand).
template <int NSRC, bool RELU, bool RES, bool HASBIAS, bool PSI>
__global__ void __launch_bounds__(512) gemm_persist(
    const float* __restrict__ ResExt, const float* __restrict__ W1,
    const float* __restrict__ W2, const float* __restrict__ bias,
    float* __restrict__ OutExt,
    int xh1_id, int xh2_id, int res_id, int out_id, int outh_id)
{
    constexpr int BN = PSI ? 256 : 128;
    constexpr int KHROWS = (PSI ? 128 : NSRC * 128) / 2;   // half2 k-pair rows
    constexpr int WSH = BN + 8;                // uint32 stride; ≡8 mod 32
    constexpr int NF = BN / 64;                // 4 (psi) or 2
    constexpr int NCHUNK = NSRC * 2;           // k64 chunks per tile
    constexpr int LOG2NC = (NCHUNK == 4) ? 2 : 1;

    extern __shared__ __align__(16) unsigned char sh_raw[];
    __half*   Xsm  = (__half*)sh_raw;                       // [4][64][72] halves
    uint32_t* Whsm = (uint32_t*)(sh_raw + 4 * XSTH * 2);    // [KHROWS][WSH]

    const __half* X1 = resolve_hbuf(xh1_id);
    const __half* X2 = (NSRC == 2) ? resolve_hbuf(xh2_id) : nullptr;
    const float* res = RES ? ((res_id < 0) ? ResExt : resolve_buf(res_id)) : nullptr;
    float* out = (out_id < 0) ? OutExt : resolve_buf(out_id);
    __half* outh = (outh_id >= 0) ? resolve_hbuf(outh_id) : nullptr;

    int tid = threadIdx.x;
    int lane = tid & 31;
    int wid = tid >> 5;
    int warp_m = wid >> 3;           // 0..1
    int warp_n = wid & 7;            // 0..7
    int g = lane >> 2;               // 0..7
    int tg = lane & 3;               // 0..3
    int b = blockIdx.x;

    uint32_t xbase;
    { uint64_t tmp = __cvta_generic_to_shared(Xsm); xbase = (uint32_t)tmp; }

    // ---- pack W into smem as half2 k-pairs: Wh[kh][n] = (W[2kh][n], W[2kh+1][n])
    {
        constexpr int NQ = KHROWS * BN / 4 / 512;
        #pragma unroll
        for (int i = 0; i < NQ; i++) {
            int f = tid + i * 512;
            int kh = f / (BN / 4);
            int c4 = (f % (BN / 4)) << 2;
            const float *r0p, *r1p;
            if (PSI) {
                const float* Wm = (c4 < 128) ? W1 : W2;
                int cc = (c4 < 128) ? c4 : c4 - 128;
                r0p = Wm + (2 * kh) * 128 + cc;
                r1p = Wm + (2 * kh + 1) * 128 + cc;
            } else if (NSRC == 2) {
                const float* Wm = (kh < 64) ? W1 : W2;
                int kk = (kh < 64) ? kh : kh - 64;
                r0p = Wm + (2 * kk) * 128 + c4;
                r1p = Wm + (2 * kk + 1) * 128 + c4;
            } else {
                r0p = W1 + (2 * kh) * 128 + c4;
                r1p = W1 + (2 * kh + 1) * 128 + c4;
            }
            float4 v0 = *(const float4*)r0p;
            float4 v1 = *(const float4*)r1p;
            uint4 u;
            u.x = h2u(__floats2half2_rn(v0.x, v1.x));
            u.y = h2u(__floats2half2_rn(v0.y, v1.y));
            u.z = h2u(__floats2half2_rn(v0.z, v1.z));
            u.w = h2u(__floats2half2_rn(v0.w, v1.w));
            *(uint4*)&Whsm[kh * WSH + c4] = u;
        }
    }

    float bv[NF][2];
    #pragma unroll
    for (int nf = 0; nf < NF; nf++) {
        int colg = warp_n * (NF * 8) + nf * 8 + tg * 2;
        bv[nf][0] = 0.f; bv[nf][1] = 0.f;
        if (PSI) {
            if (colg < 128) { bv[nf][0] = bias[colg]; bv[nf][1] = bias[colg + 1]; }
        } else if (HASBIAS) {
            bv[nf][0] = bias[colg]; bv[nf][1] = bias[colg + 1];
        }
    }

    int nt = (NTILES - b + GRID - 1) / GRID;
    int TOTAL = nt * NCHUNK;

    // X chunk (64 rows x 64 halves): 512 threads x 16B
    int xrow = tid >> 3;             // 0..63
    int xkq = (tid & 7) << 3;        // halves 0..56

    auto issue = [&](int ci) {
        int t = b + (ci >> LOG2NC) * GRID;
        int k = ci & (NCHUNK - 1);
        const __half* Xp = (NSRC == 2 && k >= 2) ? X2 : X1;
        int k0 = (k & 1) * 64;
        const __half* src = Xp + (size_t)(t * 64 + xrow) * 128 + k0 + xkq;
        uint32_t dst = xbase + ((ci & 3) * XSTH + xrow * 72 + xkq) * 2;
        CP16(dst, src);
        asm volatile("cp.async.commit_group;\n" ::);
    };

    issue(0); issue(1); issue(2);

    float C[2][NF][4];
    #pragma unroll
    for (int i = 0; i < 2; i++)
        #pragma unroll
        for (int j = 0; j < NF; j++)
            #pragma unroll
            for (int q = 0; q < 4; q++) C[i][j][q] = 0.f;

    // ldmatrix lane mapping: lanes 0-15 -> rows 0-15 col base, 16-31 -> +8 cols
    int lm_row = lane & 15;
    int lm_c8 = (lane >> 4) << 3;

    for (int ci = 0; ci < TOTAL; ci++) {
        int nxt = ci + 3; if (nxt > TOTAL - 1) nxt = TOTAL - 1;
        issue(nxt);
        asm volatile("cp.async.wait_group 3;\n" ::: "memory");
        __syncthreads();

        int k = ci & (NCHUNK - 1);
        int khchunk = (PSI ? 0 : (NSRC == 2 ? (k >> 1) * 64 : 0)) + (k & 1) * 32;
        uint32_t stg = xbase + (ci & 3) * XSTH * 2;

        #pragma unroll
        for (int kg = 0; kg < 4; kg++) {
            int kk = kg * 16;                 // half offset in stage
            uint32_t a[2][4];
            #pragma unroll
            for (int mf = 0; mf < 2; mf++) {
                int r = warp_m * 32 + mf * 16 + lm_row;
                uint32_t addr = stg + (r * 72 + kk + lm_c8) * 2;
                asm volatile(
                    "ldmatrix.sync.aligned.m8n8.x4.shared.b16 {%0,%1,%2,%3}, [%4];"
                    : "=r"(a[mf][0]), "=r"(a[mf][1]), "=r"(a[mf][2]), "=r"(a[mf][3])
                    : "r"(addr));
            }
            int khb = khchunk + kg * 8;
            #pragma unroll
            for (int nf = 0; nf < NF; nf++) {
                int col = warp_n * (NF * 8) + nf * 8 + g;
                uint32_t b0 = Whsm[(khb + tg) * WSH + col];
                uint32_t b1 = Whsm[(khb + tg + 4) * WSH + col];
                #pragma unroll
                for (int mf = 0; mf < 2; mf++) {
                    asm volatile(
                        "mma.sync.aligned.m16n8k16.row.col.f32.f16.f16.f32 "
                        "{%0,%1,%2,%3}, {%4,%5,%6,%7}, {%8,%9}, {%0,%1,%2,%3};"
                        : "+f"(C[mf][nf][0]), "+f"(C[mf][nf][1]),
                          "+f"(C[mf][nf][2]), "+f"(C[mf][nf][3])
                        : "r"(a[mf][0]), "r"(a[mf][1]), "r"(a[mf][2]), "r"(a[mf][3]),
                          "r"(b0), "r"(b1));
                }
            }
        }

        if (k == NCHUNK - 1) {
            int t = b + (ci >> LOG2NC) * GRID;
            int m0 = t * 64;
            #pragma unroll
            for (int nf = 0; nf < NF; nf++) {
                int colg = warp_n * (NF * 8) + nf * 8 + tg * 2;
                #pragma unroll
                for (int mf = 0; mf < 2; mf++) {
                    #pragma unroll
                    for (int h = 0; h < 2; h++) {
                        int m = m0 + warp_m * 32 + mf * 16 + g + h * 8;
                        float v0 = C[mf][nf][h * 2 + 0] + bv[nf][0];
                        float v1 = C[mf][nf][h * 2 + 1] + bv[nf][1];
                        if (RELU) { v0 = fmaxf(v0, 0.f); v1 = fmaxf(v1, 0.f); }
                        if (RES) {
                            float2 r = *(const float2*)&res[(size_t)m * 128 + colg];
                            v0 += r.x; v1 += r.y;
                        }
                        if (PSI && colg >= 128) {
                            *(__half2*)&g_Bh[(size_t)m * 128 + (colg - 128)] =
                                __floats2half2_rn(v0, v1);
                        } else {
                            float* outp = PSI ? g_A : out;
                            *(float2*)&outp[(size_t)m * 128 + colg] = make_float2(v0, v1);
                            if (!PSI && outh) {
                                *(__half2*)&outh[(size_t)m * 128 + colg] =
                                    __floats2half2_rn(v0, v1);
                            }
                        }
                        C[mf][nf][h * 2 + 0] = 0.f;
                        C[mf][nf][h * 2 + 1] = 0.f;
                    }
                }
            }
        }
        __syncthreads();
    }
}

// ---------------- launch ----------------
extern "C" void kernel_launch(void* const* d_in, const int* in_sizes, int n_in,
                              void* d_out, int out_size) {
    const float* x     = (const float*)d_in[0];
    const int*   ei    = (const int*)d_in[1];
    const float* psi_w = (const float*)d_in[2];
    const float* psi_b = (const float*)d_in[3];
    const float* phi_w = (const float*)d_in[4];
    const float* phi_b = (const float*)d_in[5];
    const float* dp_w  = (const float*)d_in[6];
    const float* dp_b  = (const float*)d_in[7];
    float* out = (float*)d_out;

    const int XBYTES = 4 * XSTH * 2;                   // 36864
    const int PSI_SM = XBYTES + 64 * 264 * 4;          // 104448
    const int PHI_SM = XBYTES + 128 * 136 * 4;         // 106496
    const int DP_SM  = XBYTES + 64 * 136 * 4;          // 71680

    cudaFuncSetAttribute(gemm_persist<1, false, false, true, true>,
                         cudaFuncAttributeMaxDynamicSharedMemorySize, PSI_SM);
    cudaFuncSetAttribute(gemm_persist<2, true, true, true, false>,
                         cudaFuncAttributeMaxDynamicSharedMemorySize, PHI_SM);
    cudaFuncSetAttribute(gemm_persist<1, false, false, true, false>,
                         cudaFuncAttributeMaxDynamicSharedMemorySize, DP_SM);

    zero_deg_kernel<<<(NN + 255) / 256, 256>>>();
    hist_kernel<<<(NE + 255) / 256, 256>>>(ei);
    scan_kernel<<<1, 1024>>>();
    fill_kernel<<<(NE + 255) / 256, 256>>>(ei);
    x2h_kernel<<<(NN * DD / 8 + 255) / 256, 256>>>(x);

    const int AGG_BLOCKS = (NN * 32 + 255) / 256;

    // fp16 ids: 0=g_xh0 1=g_xha 2=g_xhb 3=g_aggh ; fp32 ids: 0=g_A 3=g_xa 4=g_xb
    int xh_in = 0;
    int res_id = -1;                 // layer-0 residual source = external x
    for (int l = 0; l < LL; l++) {
        const float* psiT = psi_w + (size_t)l * 256 * 128;
        const float* psiB = psiT + 128 * 128;
        gemm_persist<1, false, false, true, true><<<GRID, 512, PSI_SM>>>(
            x, psiT, psiB, psi_b + (size_t)l * 128, nullptr,
            xh_in, -1, -1, 0, -1);
        agg_kernel<<<AGG_BLOCKS, 256>>>();
        const float* phiT = phi_w + (size_t)l * 256 * 128;
        const float* phiB = phiT + 128 * 128;
        int xo32 = 3 + (l & 1);
        int xo16 = 1 + (l & 1);
        gemm_persist<2, true, true, true, false><<<GRID, 512, PHI_SM>>>(
            x, phiT, phiB, phi_b + (size_t)l * 128, nullptr,
            xh_in, 3, res_id, xo32, xo16);
        xh_in = xo16;
        res_id = xo32;
    }
    gemm_persist<1, false, false, true, false><<<GRID, 512, DP_SM>>>(
        x, dp_w, nullptr, dp_b, out,
        xh_in, -1, -1, -1, -1);
}

// round 15
// speedup vs baseline: 1.3820x; 1.0854x over previous
#include <cuda_runtime.h>
#include <cuda_fp16.h>
#include <cstdint>
#include <cstring>

#define NN 40000
#define NE 640000
#define DD 128
#define LL 3
#define GRID 148
#define NTILES (NN / 64)          // 625 exact
#define XSTH (64 * 72)            // halves per X stage (row stride 72)

// ---------------- scratch (static __device__, no allocation) ----------------
__device__ __align__(256) float  g_A[NN * DD];     // psi-top out, fp32 (by dst)
__device__ __align__(256) __half g_Bh[NN * DD];    // psi-bot out, fp16 (by src)
__device__ __align__(256) __half g_aggh[NN * DD];  // scatter-mean, fp16
__device__ __align__(256) float  g_xa[NN * DD];    // x fp32 (residual path)
__device__ __align__(256) float  g_xb[NN * DD];
__device__ __align__(256) __half g_xh0[NN * DD];   // fp16(x input)
__device__ __align__(256) __half g_xha[NN * DD];   // fp16 x double buffers
__device__ __align__(256) __half g_xhb[NN * DD];
__device__ float g_invdeg[NN];
__device__ int   g_deg[NN];
__device__ int   g_rowptr[NN + 1];
__device__ int   g_cursor[NN];
__device__ int   g_esrc[NE];

__device__ __forceinline__ float* resolve_buf(int id) {   // fp32
    switch (id) {
        case 0: return g_A;
        case 3: return g_xa;
        case 4: return g_xb;
        default: return nullptr;
    }
}
__device__ __forceinline__ __half* resolve_hbuf(int id) { // fp16
    switch (id) {
        case 0: return g_xh0;
        case 1: return g_xha;
        case 2: return g_xhb;
        case 3: return g_aggh;
        default: return nullptr;
    }
}

__device__ __forceinline__ uint32_t h2u(__half2 h) {
    uint32_t u;
    memcpy(&u, &h, 4);
    return u;
}

#define CP16(dst_u32, src_ptr) \
    asm volatile("cp.async.cg.shared.global [%0], [%1], 16;\n" \
                 :: "r"(dst_u32), "l"(src_ptr))

// ---------------- init: zero deg + x -> fp16 ----------------
__global__ void init_kernel(const float* __restrict__ x) {
    int i = blockIdx.x * blockDim.x + threadIdx.x;
    if (i < NN) g_deg[i] = 0;
    int j = i * 8;
    if (j < NN * DD) {
        float4 v0 = *(const float4*)&x[j];
        float4 v1 = *(const float4*)&x[j + 4];
        uint4 u;
        u.x = h2u(__floats2half2_rn(v0.x, v0.y));
        u.y = h2u(__floats2half2_rn(v0.z, v0.w));
        u.z = h2u(__floats2half2_rn(v1.x, v1.y));
        u.w = h2u(__floats2half2_rn(v1.z, v1.w));
        *(uint4*)&g_xh0[j] = u;
    }
}

// ---------------- CSR build (4 edges/thread) ----------------
__global__ void hist_kernel(const int* __restrict__ ei) {
    int e = (blockIdx.x * blockDim.x + threadIdx.x) * 4;
    if (e < NE) {
        int4 d = *(const int4*)&ei[NE + e];
        if ((unsigned)d.x < NN) atomicAdd(&g_deg[d.x], 1);
        if ((unsigned)d.y < NN) atomicAdd(&g_deg[d.y], 1);
        if ((unsigned)d.z < NN) atomicAdd(&g_deg[d.z], 1);
        if ((unsigned)d.w < NN) atomicAdd(&g_deg[d.w], 1);
    }
}

__global__ void scan_kernel() {
    const int PER = 40;
    int tid = threadIdx.x;
    int lane = tid & 31, w = tid >> 5;
    int base = tid * PER;

    int total = 0;
    for (int j = 0; j < PER; j++) {
        int i = base + j;
        if (i < NN) total += g_deg[i];
    }
    int incl = total;
    #pragma unroll
    for (int off = 1; off < 32; off <<= 1) {
        int t = __shfl_up_sync(0xFFFFFFFFu, incl, off);
        if (lane >= off) incl += t;
    }
    __shared__ int wsum[32];
    if (lane == 31) wsum[w] = incl;
    __syncthreads();
    if (w == 0) {
        int v = wsum[lane];
        #pragma unroll
        for (int off = 1; off < 32; off <<= 1) {
            int t = __shfl_up_sync(0xFFFFFFFFu, v, off);
            if (lane >= off) v += t;
        }
        wsum[lane] = v;
    }
    __syncthreads();
    int run = incl - total + (w > 0 ? wsum[w - 1] : 0);
    for (int j = 0; j < PER; j++) {
        int i = base + j;
        if (i < NN) {
            int v = g_deg[i];
            g_rowptr[i] = run;
            g_cursor[i] = run;
            g_invdeg[i] = 1.0f / (float)(v > 1 ? v : 1);
            run += v;
        }
    }
    if (tid == 1023) g_rowptr[NN] = run;
}

__global__ void fill_kernel(const int* __restrict__ ei) {
    int e = (blockIdx.x * blockDim.x + threadIdx.x) * 4;
    if (e < NE) {
        int4 s = *(const int4*)&ei[e];
        int4 d = *(const int4*)&ei[NE + e];
        if ((unsigned)d.x < NN && (unsigned)s.x < NN)
            g_esrc[atomicAdd(&g_cursor[d.x], 1)] = s.x;
        if ((unsigned)d.y < NN && (unsigned)s.y < NN)
            g_esrc[atomicAdd(&g_cursor[d.y], 1)] = s.y;
        if ((unsigned)d.z < NN && (unsigned)s.z < NN)
            g_esrc[atomicAdd(&g_cursor[d.z], 1)] = s.z;
        if ((unsigned)d.w < NN && (unsigned)s.w < NN)
            g_esrc[atomicAdd(&g_cursor[d.w], 1)] = s.w;
    }
}

// ---------------- edge aggregation: warp/node, fp16 B, fp16 out ------------
__global__ void agg_kernel() {
    int gt = blockIdx.x * blockDim.x + threadIdx.x;
    int node = gt >> 5;
    int lane = threadIdx.x & 31;
    if (node >= NN) return;
    int c = lane << 2;
    const float4 a = *(const float4*)&g_A[node * DD + c];
    float4 acc = make_float4(0.f, 0.f, 0.f, 0.f);
    int e0 = g_rowptr[node];
    int e1 = g_rowptr[node + 1];
    #pragma unroll 4
    for (int e = e0; e < e1; ++e) {
        int s = g_esrc[e];
        uint2 hb = *(const uint2*)&g_Bh[s * DD + c];
        float2 b01 = __half22float2(*(__half2*)&hb.x);
        float2 b23 = __half22float2(*(__half2*)&hb.y);
        acc.x += fmaxf(a.x + b01.x, 0.f);
        acc.y += fmaxf(a.y + b01.y, 0.f);
        acc.z += fmaxf(a.z + b23.x, 0.f);
        acc.w += fmaxf(a.w + b23.y, 0.f);
    }
    float id = g_invdeg[node];
    uint2 o;
    o.x = h2u(__floats2half2_rn(acc.x * id, acc.y * id));
    o.y = h2u(__floats2half2_rn(acc.z * id, acc.w * id));
    *(uint2*)&g_aggh[node * DD + c] = o;
}

// ---------------- psi1: persistent W-resident pipelined fp16 GEMM -----------
// [A|B] = Xh @ [W1|W2]; A fp32 (+bias) -> g_A, B fp16 -> g_Bh
__global__ void __launch_bounds__(512) psi_gemm(
    const float* __restrict__ W1, const float* __restrict__ W2,
    const float* __restrict__ bias, int xh1_id)
{
    constexpr int BN = 256;
    constexpr int WSH = 264;
    constexpr int NF = 4;

    extern __shared__ __align__(16) unsigned char sh_raw[];
    __half*   Xsm  = (__half*)sh_raw;                       // [4][64][72]
    uint32_t* Whsm = (uint32_t*)(sh_raw + 4 * XSTH * 2);    // [64][264]

    const __half* X1 = resolve_hbuf(xh1_id);

    int tid = threadIdx.x;
    int lane = tid & 31;
    int wid = tid >> 5;
    int warp_m = wid >> 3;
    int warp_n = wid & 7;
    int g = lane >> 2;
    int tg = lane & 3;
    int b = blockIdx.x;

    uint32_t xbase;
    { uint64_t tmp = __cvta_generic_to_shared(Xsm); xbase = (uint32_t)tmp; }

    #pragma unroll
    for (int i = 0; i < 8; i++) {
        int f = tid + i * 512;
        int kh = f >> 6;
        int c4 = (f & 63) << 2;
        const float* Wm = (c4 < 128) ? W1 : W2;
        int cc = c4 & 127;
        float4 v0 = *(const float4*)(Wm + (2 * kh) * 128 + cc);
        float4 v1 = *(const float4*)(Wm + (2 * kh + 1) * 128 + cc);
        uint4 u;
        u.x = h2u(__floats2half2_rn(v0.x, v1.x));
        u.y = h2u(__floats2half2_rn(v0.y, v1.y));
        u.z = h2u(__floats2half2_rn(v0.z, v1.z));
        u.w = h2u(__floats2half2_rn(v0.w, v1.w));
        *(uint4*)&Whsm[kh * WSH + c4] = u;
    }

    float bv[NF][2];
    #pragma unroll
    for (int nf = 0; nf < NF; nf++) {
        int colg = warp_n * 32 + nf * 8 + tg * 2;
        bv[nf][0] = (colg < 128) ? bias[colg] : 0.f;
        bv[nf][1] = (colg < 128) ? bias[colg + 1] : 0.f;
    }

    int nt = (NTILES - b + GRID - 1) / GRID;
    int TOTAL = nt * 2;              // 2 k64 chunks per tile

    int xrow = tid >> 3;
    int xkq = (tid & 7) << 3;

    auto issue = [&](int ci) {
        int t = b + (ci >> 1) * GRID;
        int k0 = (ci & 1) * 64;
        const __half* src = X1 + (size_t)(t * 64 + xrow) * 128 + k0 + xkq;
        uint32_t dst = xbase + ((ci & 3) * XSTH + xrow * 72 + xkq) * 2;
        CP16(dst, src);
        asm volatile("cp.async.commit_group;\n" ::);
    };

    issue(0); issue(1); if (TOTAL > 2) issue(2);

    float C[2][NF][4];
    #pragma unroll
    for (int i = 0; i < 2; i++)
        #pragma unroll
        for (int j = 0; j < NF; j++)
            #pragma unroll
            for (int q = 0; q < 4; q++) C[i][j][q] = 0.f;

    int lm_row = lane & 15;
    int lm_c8 = (lane >> 4) << 3;

    for (int ci = 0; ci < TOTAL; ci++) {
        int nxt = ci + 3; if (nxt > TOTAL - 1) nxt = TOTAL - 1;
        issue(nxt);
        asm volatile("cp.async.wait_group 3;\n" ::: "memory");
        __syncthreads();

        int k = ci & 1;
        int khchunk = k * 32;
        uint32_t stg = xbase + (ci & 3) * XSTH * 2;

        #pragma unroll
        for (int kg = 0; kg < 4; kg++) {
            int kk = kg * 16;
            uint32_t a[2][4];
            #pragma unroll
            for (int mf = 0; mf < 2; mf++) {
                int r = warp_m * 32 + mf * 16 + lm_row;
                uint32_t addr = stg + (r * 72 + kk + lm_c8) * 2;
                asm volatile(
                    "ldmatrix.sync.aligned.m8n8.x4.shared.b16 {%0,%1,%2,%3}, [%4];"
                    : "=r"(a[mf][0]), "=r"(a[mf][1]), "=r"(a[mf][2]), "=r"(a[mf][3])
                    : "r"(addr));
            }
            int khb = khchunk + kg * 8;
            #pragma unroll
            for (int nf = 0; nf < NF; nf++) {
                int col = warp_n * 32 + nf * 8 + g;
                uint32_t b0 = Whsm[(khb + tg) * WSH + col];
                uint32_t b1 = Whsm[(khb + tg + 4) * WSH + col];
                #pragma unroll
                for (int mf = 0; mf < 2; mf++) {
                    asm volatile(
                        "mma.sync.aligned.m16n8k16.row.col.f32.f16.f16.f32 "
                        "{%0,%1,%2,%3}, {%4,%5,%6,%7}, {%8,%9}, {%0,%1,%2,%3};"
                        : "+f"(C[mf][nf][0]), "+f"(C[mf][nf][1]),
                          "+f"(C[mf][nf][2]), "+f"(C[mf][nf][3])
                        : "r"(a[mf][0]), "r"(a[mf][1]), "r"(a[mf][2]), "r"(a[mf][3]),
                          "r"(b0), "r"(b1));
                }
            }
        }

        if (k == 1) {
            int t = b + (ci >> 1) * GRID;
            int m0 = t * 64;
            #pragma unroll
            for (int nf = 0; nf < NF; nf++) {
                int colg = warp_n * 32 + nf * 8 + tg * 2;
                #pragma unroll
                for (int mf = 0; mf < 2; mf++) {
                    #pragma unroll
                    for (int h = 0; h < 2; h++) {
                        int m = m0 + warp_m * 32 + mf * 16 + g + h * 8;
                        float v0 = C[mf][nf][h * 2 + 0] + bv[nf][0];
                        float v1 = C[mf][nf][h * 2 + 1] + bv[nf][1];
                        if (colg < 128) {
                            *(float2*)&g_A[(size_t)m * 128 + colg] = make_float2(v0, v1);
                        } else {
                            *(__half2*)&g_Bh[(size_t)m * 128 + (colg - 128)] =
                                __floats2half2_rn(v0, v1);
                        }
                        C[mf][nf][h * 2 + 0] = 0.f;
                        C[mf][nf][h * 2 + 1] = 0.f;
                    }
                }
            }
        }
        __syncthreads();
    }
}

// ---------------- fused phi + (psi | dp) ------------------------------------
// Phase1: x' = relu(xh@Wphi1 + aggh@Wphi2 + phi_b) + res  -> fp32 out32,
//         fp16 outh (optional), fp16 smem tile.
// Phase2 (P2=0, psi): [A|B] = tile @ [Wp2a|Wp2b]; A fp32+psi_b -> g_A, B -> g_Bh
// Phase2 (P2=1, dp):  OutExt = tile @ Wp2a + p2_bias (fp32)
template <int P2>
__global__ void __launch_bounds__(512) phi_fused(
    const float* __restrict__ ResExt,
    const float* __restrict__ Wphi1, const float* __restrict__ Wphi2,
    const float* __restrict__ phi_bias,
    const float* __restrict__ Wp2a, const float* __restrict__ Wp2b,
    const float* __restrict__ p2_bias,
    float* __restrict__ OutExt,
    int xh1_id, int res_id, int out32_id, int outh_id)
{
    constexpr int WSH = 136;                    // phi W stride (u32)
    constexpr int NF2 = (P2 == 0) ? 4 : 2;
    constexpr int WSH2 = (P2 == 0) ? 264 : 136;
    constexpr int WPHI_OFF = 4 * XSTH * 2;                 // 36864
    constexpr int WP2_OFF = WPHI_OFF + 128 * WSH * 4;      // +69632
    constexpr int TILE_OFF = WP2_OFF + 64 * WSH2 * 4;
    constexpr int TS = 136;                     // tile stride (halves)

    extern __shared__ __align__(16) unsigned char sh_raw[];
    __half*   Xsm    = (__half*)sh_raw;
    uint32_t* Wphism = (uint32_t*)(sh_raw + WPHI_OFF);
    uint32_t* Wp2sm  = (uint32_t*)(sh_raw + WP2_OFF);
    __half*   Tile   = (__half*)(sh_raw + TILE_OFF);

    const __half* X1 = resolve_hbuf(xh1_id);
    const __half* X2 = g_aggh;
    const float* res = (res_id < 0) ? ResExt : resolve_buf(res_id);
    float* out32 = resolve_buf(out32_id);
    __half* outh = (outh_id >= 0) ? resolve_hbuf(outh_id) : nullptr;

    int tid = threadIdx.x;
    int lane = tid & 31;
    int wid = tid >> 5;
    int warp_m = wid >> 3;
    int warp_n = wid & 7;
    int g = lane >> 2;
    int tg = lane & 3;
    int b = blockIdx.x;

    uint32_t xbase, tbase;
    { uint64_t tmp = __cvta_generic_to_shared(Xsm); xbase = (uint32_t)tmp; }
    { uint64_t tmp = __cvta_generic_to_shared(Tile); tbase = (uint32_t)tmp; }

    // pack phi W: rows kh 0..127 (k-pairs of 2x128 stacked W1|W2), cols 0..127
    #pragma unroll
    for (int i = 0; i < 8; i++) {
        int f = tid + i * 512;
        int kh = f >> 5;
        int c4 = (f & 31) << 2;
        const float* Wm = (kh < 64) ? Wphi1 : Wphi2;
        int kk = kh & 63;
        float4 v0 = *(const float4*)(Wm + (2 * kk) * 128 + c4);
        float4 v1 = *(const float4*)(Wm + (2 * kk + 1) * 128 + c4);
        uint4 u;
        u.x = h2u(__floats2half2_rn(v0.x, v1.x));
        u.y = h2u(__floats2half2_rn(v0.y, v1.y));
        u.z = h2u(__floats2half2_rn(v0.z, v1.z));
        u.w = h2u(__floats2half2_rn(v0.w, v1.w));
        *(uint4*)&Wphism[kh * WSH + c4] = u;
    }
    // pack phase2 W
    if (P2 == 0) {
        #pragma unroll
        for (int i = 0; i < 8; i++) {
            int f = tid + i * 512;
            int kh = f >> 6;
            int c4 = (f & 63) << 2;
            const float* Wm = (c4 < 128) ? Wp2a : Wp2b;
            int cc = c4 & 127;
            float4 v0 = *(const float4*)(Wm + (2 * kh) * 128 + cc);
            float4 v1 = *(const float4*)(Wm + (2 * kh + 1) * 128 + cc);
            uint4 u;
            u.x = h2u(__floats2half2_rn(v0.x, v1.x));
            u.y = h2u(__floats2half2_rn(v0.y, v1.y));
            u.z = h2u(__floats2half2_rn(v0.z, v1.z));
            u.w = h2u(__floats2half2_rn(v0.w, v1.w));
            *(uint4*)&Wp2sm[kh * WSH2 + c4] = u;
        }
    } else {
        #pragma unroll
        for (int i = 0; i < 4; i++) {
            int f = tid + i * 512;
            int kh = f >> 5;
            int c4 = (f & 31) << 2;
            float4 v0 = *(const float4*)(Wp2a + (2 * kh) * 128 + c4);
            float4 v1 = *(const float4*)(Wp2a + (2 * kh + 1) * 128 + c4);
            uint4 u;
            u.x = h2u(__floats2half2_rn(v0.x, v1.x));
            u.y = h2u(__floats2half2_rn(v0.y, v1.y));
            u.z = h2u(__floats2half2_rn(v0.z, v1.z));
            u.w = h2u(__floats2half2_rn(v0.w, v1.w));
            *(uint4*)&Wp2sm[kh * WSH2 + c4] = u;
        }
    }

    float bv[2][2];
    #pragma unroll
    for (int nf = 0; nf < 2; nf++) {
        int colg = warp_n * 16 + nf * 8 + tg * 2;
        bv[nf][0] = phi_bias[colg];
        bv[nf][1] = phi_bias[colg + 1];
    }
    float bv2[NF2][2];
    #pragma unroll
    for (int nf = 0; nf < NF2; nf++) {
        int colg = warp_n * (NF2 * 8) + nf * 8 + tg * 2;
        if (P2 == 0) {
            bv2[nf][0] = (colg < 128) ? p2_bias[colg] : 0.f;
            bv2[nf][1] = (colg < 128) ? p2_bias[colg + 1] : 0.f;
        } else {
            bv2[nf][0] = p2_bias[colg];
            bv2[nf][1] = p2_bias[colg + 1];
        }
    }

    int nt = (NTILES - b + GRID - 1) / GRID;
    int TOTAL = nt * 4;              // 4 k64 chunks per tile (2 sources)

    int xrow = tid >> 3;
    int xkq = (tid & 7) << 3;

    auto issue = [&](int ci) {
        int t = b + (ci >> 2) * GRID;
        int k = ci & 3;
        const __half* Xp = (k >= 2) ? X2 : X1;
        int k0 = (k & 1) * 64;
        const __half* src = Xp + (size_t)(t * 64 + xrow) * 128 + k0 + xkq;
        uint32_t dst = xbase + ((ci & 3) * XSTH + xrow * 72 + xkq) * 2;
        CP16(dst, src);
        asm volatile("cp.async.commit_group;\n" ::);
    };

    issue(0); issue(1); issue(2);

    float C[2][2][4];
    #pragma unroll
    for (int i = 0; i < 2; i++)
        #pragma unroll
        for (int j = 0; j < 2; j++)
            #pragma unroll
            for (int q = 0; q < 4; q++) C[i][j][q] = 0.f;

    int lm_row = lane & 15;
    int lm_c8 = (lane >> 4) << 3;

    for (int ci = 0; ci < TOTAL; ci++) {
        int nxt = ci + 3; if (nxt > TOTAL - 1) nxt = TOTAL - 1;
        issue(nxt);
        asm volatile("cp.async.wait_group 3;\n" ::: "memory");
        __syncthreads();

        int k = ci & 3;
        int khchunk = (k >> 1) * 64 + (k & 1) * 32;
        uint32_t stg = xbase + (ci & 3) * XSTH * 2;

        #pragma unroll
        for (int kg = 0; kg < 4; kg++) {
            int kk = kg * 16;
            uint32_t a[2][4];
            #pragma unroll
            for (int mf = 0; mf < 2; mf++) {
                int r = warp_m * 32 + mf * 16 + lm_row;
                uint32_t addr = stg + (r * 72 + kk + lm_c8) * 2;
                asm volatile(
                    "ldmatrix.sync.aligned.m8n8.x4.shared.b16 {%0,%1,%2,%3}, [%4];"
                    : "=r"(a[mf][0]), "=r"(a[mf][1]), "=r"(a[mf][2]), "=r"(a[mf][3])
                    : "r"(addr));
            }
            int khb = khchunk + kg * 8;
            #pragma unroll
            for (int nf = 0; nf < 2; nf++) {
                int col = warp_n * 16 + nf * 8 + g;
                uint32_t b0 = Wphism[(khb + tg) * WSH + col];
                uint32_t b1 = Wphism[(khb + tg + 4) * WSH + col];
                #pragma unroll
                for (int mf = 0; mf < 2; mf++) {
                    asm volatile(
                        "mma.sync.aligned.m16n8k16.row.col.f32.f16.f16.f32 "
                        "{%0,%1,%2,%3}, {%4,%5,%6,%7}, {%8,%9}, {%0,%1,%2,%3};"
                        : "+f"(C[mf][nf][0]), "+f"(C[mf][nf][1]),
                          "+f"(C[mf][nf][2]), "+f"(C[mf][nf][3])
                        : "r"(a[mf][0]), "r"(a[mf][1]), "r"(a[mf][2]), "r"(a[mf][3]),
                          "r"(b0), "r"(b1));
                }
            }
        }

        if (k == 3) {
            int t = b + (ci >> 2) * GRID;
            int m0 = t * 64;
            // phase1 epilogue: relu + residual; write fp32, fp16, tile
            #pragma unroll
            for (int nf = 0; nf < 2; nf++) {
                int colg = warp_n * 16 + nf * 8 + tg * 2;
                #pragma unroll
                for (int mf = 0; mf < 2; mf++) {
                    #pragma unroll
                    for (int h = 0; h < 2; h++) {
                        int ml = warp_m * 32 + mf * 16 + g + h * 8;
                        int m = m0 + ml;
                        float v0 = C[mf][nf][h * 2 + 0] + bv[nf][0];
                        float v1 = C[mf][nf][h * 2 + 1] + bv[nf][1];
                        v0 = fmaxf(v0, 0.f); v1 = fmaxf(v1, 0.f);
                        float2 r = *(const float2*)&res[(size_t)m * 128 + colg];
                        v0 += r.x; v1 += r.y;
                        *(float2*)&out32[(size_t)m * 128 + colg] = make_float2(v0, v1);
                        __half2 hv = __floats2half2_rn(v0, v1);
                        if (outh)
                            *(__half2*)&outh[(size_t)m * 128 + colg] = hv;
                        *(__half2*)&Tile[ml * TS + colg] = hv;
                        C[mf][nf][h * 2 + 0] = 0.f;
                        C[mf][nf][h * 2 + 1] = 0.f;
                    }
                }
            }
            __syncthreads();
            // ---- phase2: tile @ Wp2 ----
            float C2[2][NF2][4];
            #pragma unroll
            for (int i = 0; i < 2; i++)
                #pragma unroll
                for (int j = 0; j < NF2; j++)
                    #pragma unroll
                    for (int q = 0; q < 4; q++) C2[i][j][q] = 0.f;

            #pragma unroll
            for (int kg = 0; kg < 8; kg++) {
                int kk = kg * 16;
                uint32_t a[2][4];
                #pragma unroll
                for (int mf = 0; mf < 2; mf++) {
                    int r = warp_m * 32 + mf * 16 + lm_row;
                    uint32_t addr = tbase + (r * TS + kk + lm_c8) * 2;
                    asm volatile(
                        "ldmatrix.sync.aligned.m8n8.x4.shared.b16 {%0,%1,%2,%3}, [%4];"
                        : "=r"(a[mf][0]), "=r"(a[mf][1]), "=r"(a[mf][2]), "=r"(a[mf][3])
                        : "r"(addr));
                }
                int khb = kg * 8;
                #pragma unroll
                for (int nf = 0; nf < NF2; nf++) {
                    int col = warp_n * (NF2 * 8) + nf * 8 + g;
                    uint32_t b0 = Wp2sm[(khb + tg) * WSH2 + col];
                    uint32_t b1 = Wp2sm[(khb + tg + 4) * WSH2 + col];
                    #pragma unroll
                    for (int mf = 0; mf < 2; mf++) {
                        asm volatile(
                            "mma.sync.aligned.m16n8k16.row.col.f32.f16.f16.f32 "
                            "{%0,%1,%2,%3}, {%4,%5,%6,%7}, {%8,%9}, {%0,%1,%2,%3};"
                            : "+f"(C2[mf][nf][0]), "+f"(C2[mf][nf][1]),
                              "+f"(C2[mf][nf][2]), "+f"(C2[mf][nf][3])
                            : "r"(a[mf][0]), "r"(a[mf][1]), "r"(a[mf][2]), "r"(a[mf][3]),
                              "r"(b0), "r"(b1));
                    }
                }
            }
            // phase2 epilogue
            #pragma unroll
            for (int nf = 0; nf < NF2; nf++) {
                int colg = warp_n * (NF2 * 8) + nf * 8 + tg * 2;
                #pragma unroll
                for (int mf = 0; mf < 2; mf++) {
                    #pragma unroll
                    for (int h = 0; h < 2; h++) {
                        int m = m0 + warp_m * 32 + mf * 16 + g + h * 8;
                        float v0 = C2[mf][nf][h * 2 + 0] + bv2[nf][0];
                        float v1 = C2[mf][nf][h * 2 + 1] + bv2[nf][1];
                        if (P2 == 0) {
                            if (colg < 128) {
                                *(float2*)&g_A[(size_t)m * 128 + colg] =
                                    make_float2(v0, v1);
                            } else {
                                *(__half2*)&g_Bh[(size_t)m * 128 + (colg - 128)] =
                                    __floats2half2_rn(v0, v1);
                            }
                        } else {
                            *(float2*)&OutExt[(size_t)m * 128 + colg] =
                                make_float2(v0, v1);
                        }
                    }
                }
            }
        }
        __syncthreads();
    }
}

// ---------------- launch ----------------
extern "C" void kernel_launch(void* const* d_in, const int* in_sizes, int n_in,
                              void* d_out, int out_size) {
    const float* x     = (const float*)d_in[0];
    const int*   ei    = (const int*)d_in[1];
    const float* psi_w = (const float*)d_in[2];
    const float* psi_b = (const float*)d_in[3];
    const float* phi_w = (const float*)d_in[4];
    const float* phi_b = (const float*)d_in[5];
    const float* dp_w  = (const float*)d_in[6];
    const float* dp_b  = (const float*)d_in[7];
    float* out = (float*)d_out;

    const int XBYTES   = 4 * XSTH * 2;                     // 36864
    const int PSI_SM   = XBYTES + 64 * 264 * 4;            // 104448
    const int FUSE_PSI = XBYTES + 128 * 136 * 4 + 64 * 264 * 4 + 64 * 136 * 2; // 191488
    const int FUSE_DP  = XBYTES + 128 * 136 * 4 + 64 * 136 * 4 + 64 * 136 * 2; // 158720

    cudaFuncSetAttribute(psi_gemm,
                         cudaFuncAttributeMaxDynamicSharedMemorySize, PSI_SM);
    cudaFuncSetAttribute(phi_fused<0>,
                         cudaFuncAttributeMaxDynamicSharedMemorySize, FUSE_PSI);
    cudaFuncSetAttribute(phi_fused<1>,
                         cudaFuncAttributeMaxDynamicSharedMemorySize, FUSE_DP);

    init_kernel<<<(NN * DD / 8 + 255) / 256, 256>>>(x);
    hist_kernel<<<(NE / 4 + 255) / 256, 256>>>(ei);
    scan_kernel<<<1, 1024>>>();
    fill_kernel<<<(NE / 4 + 255) / 256, 256>>>(ei);

    const int AGG_BLOCKS = (NN * 32 + 255) / 256;

    // layer 1 psi
    const float* psiT0 = psi_w;
    psi_gemm<<<GRID, 512, PSI_SM>>>(psiT0, psiT0 + 128 * 128, psi_b, 0);

    // fp16 ids: 0=g_xh0 1=g_xha 2=g_xhb 3=g_aggh ; fp32 ids: 0=g_A 3=g_xa 4=g_xb
    int xh_in = 0;
    int res_id = -1;
    for (int l = 0; l < LL; l++) {
        agg_kernel<<<AGG_BLOCKS, 256>>>();
        const float* phiT = phi_w + (size_t)l * 256 * 128;
        const float* phiB = phiT + 128 * 128;
        if (l < LL - 1) {
            const float* psiT = psi_w + (size_t)(l + 1) * 256 * 128;
            const float* psiB = psiT + 128 * 128;
            int xo32 = 3 + (l & 1);
            int xo16 = 1 + (l & 1);
            phi_fused<0><<<GRID, 512, FUSE_PSI>>>(
                x, phiT, phiB, phi_b + (size_t)l * 128,
                psiT, psiB, psi_b + (size_t)(l + 1) * 128, nullptr,
                xh_in, res_id, xo32, xo16);
            xh_in = xo16;
            res_id = xo32;
        } else {
            phi_fused<1><<<GRID, 512, FUSE_DP>>>(
                x, phiT, phiB, phi_b + (size_t)l * 128,
                dp_w, nullptr, dp_b, out,
                xh_in, res_id, 3 + (l & 1), -1);
        }
    }
}